// round 3
// baseline (speedup 1.0000x reference)
#include <cuda_runtime.h>
#include <math.h>

#define NN       1024
#define NEVALC   131072
#define NPOLES   8
#define NGROUPS  256          // 4 nodes per group
#define PI_D     3.14159265358979323846
#define LOGC     700.0f       // fixed log-shift (cancels in num/den); keeps expf in range

typedef unsigned long long ull;

// ---------------- scratch (no allocations allowed) ----------------
__device__ ulonglong2 g_coef[NGROUPS * 7];   // 14 packed-duplicated f32x2 coeffs per group

// ---------------- packed f32x2 helpers (sm_103a) ----------------
__device__ __forceinline__ ull f2fma(ull a, ull b, ull c) {
    ull d; asm("fma.rn.f32x2 %0,%1,%2,%3;" : "=l"(d) : "l"(a), "l"(b), "l"(c)); return d;
}
__device__ __forceinline__ ull f2add(ull a, ull b) {
    ull d; asm("add.rn.f32x2 %0,%1,%2;" : "=l"(d) : "l"(a), "l"(b)); return d;
}
__device__ __forceinline__ ull pk2(float lo, float hi) {
    ull r; asm("mov.b64 %0,{%1,%2};" : "=l"(r) : "f"(lo), "f"(hi)); return r;
}
__device__ __forceinline__ void upk2(ull v, float& lo, float& hi) {
    asm("mov.b64 {%0,%1},%2;" : "=f"(lo), "=f"(hi) : "l"(v));
}
__device__ __forceinline__ float frcp(float a) {
    float r; asm("rcp.approx.f32 %0,%1;" : "=f"(r) : "f"(a)); return r;
}

// ---------------- P0: fused prep — nodes + weights + group coefficients --------------
// grid 128 x block 256. Block b owns nodes 8b..8b+7 and groups 2b, 2b+1.
// (a) every block recomputes all 1024 Chebyshev nodes into smem (no global dep)
// (b) warp w computes the f32 log-sum weight of node 8b+w (reference math; the
//     max-normalization in the reference is a COMMON factor across nodes and
//     cancels in num/den, so a fixed LOGC shift replaces the global reduction)
// (c) threads 0..1 build the fp64 group-rational coefficients and pack f32x2.
//     Group g: nodes 4g..4g+3, local var t = x - c:
//       Q(t)  = prod (t - d_i)                     (monic quartic)
//       Pv(t) = sum v_i*w_i * prod_{j!=i}(t - d_j) (cubic)
//       Pw(t) = sum     w_i * prod_{j!=i}(t - d_j) (cubic)
__global__ __launch_bounds__(256) void k_prep(const float* __restrict__ vals,
                                              const float* __restrict__ pr,
                                              const float* __restrict__ pim) {
    __shared__ float snodes[NN];
    __shared__ float sw[8];
    int tid = threadIdx.x;

    // (a) nodes: double cos -> f32 (same formula as previous passing rounds)
    #pragma unroll
    for (int i = tid; i < NN; i += 256) {
        double t = (double)i / 1023.0;
        snodes[i] = (float)cos(PI_D * t);
    }
    __syncthreads();

    // (b) weights: one warp per node
    int w  = tid >> 5;
    int ln = tid & 31;
    int j  = blockIdx.x * 8 + w;
    float nj = snodes[j];
    float s = 0.f;
    #pragma unroll 8
    for (int i = ln; i < NN; i += 32)
        if (i != j) s += logf(fabsf(nj - snodes[i]));
    #pragma unroll
    for (int off = 16; off; off >>= 1) s += __shfl_xor_sync(0xffffffffu, s, off);
    if (ln == 0) {
        float ps = 0.f;
        #pragma unroll
        for (int p = 0; p < NPOLES; p++) {
            float dr = nj - pr[p];
            ps += logf(dr * dr + pim[p] * pim[p]);
        }
        float wv = expf(ps - s - LOGC);
        sw[w] = (j & 1) ? -wv : wv;     // sign = (-1)^j (nodes strictly descending)
    }
    __syncthreads();

    // (c) coefficients: 2 groups per block
    if (tid < 2) {
        int g = blockIdx.x * 2 + tid;
        double n[4], d[4], u[4], uv[4];
        #pragma unroll
        for (int i = 0; i < 4; i++) n[i] = (double)snodes[4 * g + i];
        float cf = (float)(0.25 * (n[0] + n[1] + n[2] + n[3]));
        #pragma unroll
        for (int i = 0; i < 4; i++) {
            d[i]  = n[i] - (double)cf;
            u[i]  = (double)sw[4 * tid + i];
            uv[i] = u[i] * (double)vals[4 * g + i];
        }
        double e1 = d[0] + d[1] + d[2] + d[3];
        double e2 = d[0]*d[1] + d[0]*d[2] + d[0]*d[3] + d[1]*d[2] + d[1]*d[3] + d[2]*d[3];
        double e3 = d[0]*d[1]*d[2] + d[0]*d[1]*d[3] + d[0]*d[2]*d[3] + d[1]*d[2]*d[3];
        double e4 = d[0]*d[1]*d[2]*d[3];
        double pv3 = 0, pv2 = 0, pv1 = 0, pv0 = 0;
        double pw3 = 0, pw2 = 0, pw1 = 0, pw0 = 0;
        #pragma unroll
        for (int i = 0; i < 4; i++) {
            double s1 = e1 - d[i];          // elementary syms of the 3 other roots
            double s2 = e2 - d[i] * s1;
            double s3 = e3 - d[i] * s2;
            pv3 += uv[i];  pv2 -= uv[i] * s1;  pv1 += uv[i] * s2;  pv0 -= uv[i] * s3;
            pw3 += u[i];   pw2 -= u[i]  * s1;  pw1 += u[i]  * s2;  pw0 -= u[i]  * s3;
        }
        ull* cc = (ull*)g_coef + (size_t)g * 14;
        float f;
        f = -cf;          cc[0]  = pk2(f, f);
        f = (float)(-e1); cc[1]  = pk2(f, f);   // q3
        f = (float)( e2); cc[2]  = pk2(f, f);   // q2
        f = (float)(-e3); cc[3]  = pk2(f, f);   // q1
        f = (float)( e4); cc[4]  = pk2(f, f);   // q0
        f = (float)pv3;   cc[5]  = pk2(f, f);
        f = (float)pv2;   cc[6]  = pk2(f, f);
        f = (float)pv1;   cc[7]  = pk2(f, f);
        f = (float)pv0;   cc[8]  = pk2(f, f);
        f = (float)pw3;   cc[9]  = pk2(f, f);
        f = (float)pw2;   cc[10] = pk2(f, f);
        f = (float)pw1;   cc[11] = pk2(f, f);
        f = (float)pw0;   cc[12] = pk2(f, f);
        cc[13] = 0ull;                          // pad to 7 x 16B
    }
}

// ---------------- main eval: 8 points (4 packed f32x2 pairs) per thread --------------
// grid 128 x block 128 -> 1 block/SM, 1 warp/SMSP. The 12+ independent Horner
// chains per group provide the ILP for a single warp to saturate the fma pipe.
__global__ __launch_bounds__(128) void k_eval(const float* __restrict__ x,
                                              float* __restrict__ out) {
    __shared__ ulonglong2 sc[NGROUPS * 7];   // 28 KB, broadcast reads
    {
        const uint4* src = (const uint4*)g_coef;
        uint4* dst = (uint4*)sc;
        #pragma unroll
        for (int i = threadIdx.x; i < NGROUPS * 7; i += 128) dst[i] = src[i];
    }
    __syncthreads();

    int idx = blockIdx.x * 128 + threadIdx.x;       // 8 consecutive points
    float4 xv0 = ((const float4*)x)[idx * 2];
    float4 xv1 = ((const float4*)x)[idx * 2 + 1];
    ull xp[4];
    xp[0] = pk2(xv0.x, xv0.y);
    xp[1] = pk2(xv0.z, xv0.w);
    xp[2] = pk2(xv1.x, xv1.y);
    xp[3] = pk2(xv1.z, xv1.w);
    ull num[4] = {0ull, 0ull, 0ull, 0ull};
    ull den[4] = {0ull, 0ull, 0ull, 0ull};
    const ulonglong2* cp = sc;

    #pragma unroll 2
    for (int g = 0; g < NGROUPS; g++) {
        ulonglong2 c0 = cp[0], c1 = cp[1], c2 = cp[2], c3 = cp[3],
                   c4 = cp[4], c5 = cp[5], c6 = cp[6];
        cp += 7;
        #pragma unroll
        for (int p = 0; p < 4; p++) {
            ull t = f2add(xp[p], c0.x);             // t = x - c (exact near group)
            ull q = f2add(t, c0.y);                 // monic quartic Horner
            q = f2fma(q, t, c1.x);
            q = f2fma(q, t, c1.y);
            q = f2fma(q, t, c2.x);
            ull pv = f2fma(c2.y, t, c3.x);          // cubic Horner (num)
            pv = f2fma(pv, t, c3.y);
            pv = f2fma(pv, t, c4.x);
            ull pw = f2fma(c4.y, t, c5.x);          // cubic Horner (den)
            pw = f2fma(pw, t, c5.y);
            pw = f2fma(pw, t, c6.x);
            float ql, qh;
            upk2(q, ql, qh);
            ull r = pk2(frcp(ql), frcp(qh));        // 1 MUFU per 4 nodes per point
            num[p] = f2fma(pv, r, num[p]);
            den[p] = f2fma(pw, r, den[p]);
        }
    }
    float n0, n1, d0, d1;
    float4 o;
    upk2(num[0], n0, n1); upk2(den[0], d0, d1);
    o.x = n0 * frcp(d0);  o.y = n1 * frcp(d1);
    upk2(num[1], n0, n1); upk2(den[1], d0, d1);
    o.z = n0 * frcp(d0);  o.w = n1 * frcp(d1);
    ((float4*)out)[idx * 2] = o;
    upk2(num[2], n0, n1); upk2(den[2], d0, d1);
    o.x = n0 * frcp(d0);  o.y = n1 * frcp(d1);
    upk2(num[3], n0, n1); upk2(den[3], d0, d1);
    o.z = n0 * frcp(d0);  o.w = n1 * frcp(d1);
    ((float4*)out)[idx * 2 + 1] = o;
}

// ---------------- launch ----------------
extern "C" void kernel_launch(void* const* d_in, const int* in_sizes, int n_in,
                              void* d_out, int out_size) {
    const float* x    = (const float*)d_in[0];
    const float* vals = (const float*)d_in[1];
    const float* pr   = (const float*)d_in[2];
    const float* pim  = (const float*)d_in[3];
    float* out = (float*)d_out;

    k_prep<<<128, 256>>>(vals, pr, pim);
    k_eval<<<128, 128>>>(x, out);
}

// round 4
// speedup vs baseline: 1.1775x; 1.1775x over previous
#include <cuda_runtime.h>
#include <math.h>

#define NN       1024
#define NEVALC   131072
#define NPOLES   8
#define NGROUPS  256          // 4 nodes per group
#define PI_D     3.14159265358979323846
#define LOGC     700.0f       // fixed log-shift (cancels in num/den); keeps expf in range

typedef unsigned long long ull;

// ---------------- scratch (no allocations allowed) ----------------
__device__ ulonglong2 g_coef[NGROUPS * 7];   // 14 packed-duplicated f32x2 coeffs per group

// ---------------- packed f32x2 helpers (sm_103a) ----------------
__device__ __forceinline__ ull f2fma(ull a, ull b, ull c) {
    ull d; asm("fma.rn.f32x2 %0,%1,%2,%3;" : "=l"(d) : "l"(a), "l"(b), "l"(c)); return d;
}
__device__ __forceinline__ ull f2add(ull a, ull b) {
    ull d; asm("add.rn.f32x2 %0,%1,%2;" : "=l"(d) : "l"(a), "l"(b)); return d;
}
__device__ __forceinline__ ull pk2(float lo, float hi) {
    ull r; asm("mov.b64 %0,{%1,%2};" : "=l"(r) : "f"(lo), "f"(hi)); return r;
}
__device__ __forceinline__ void upk2(ull v, float& lo, float& hi) {
    asm("mov.b64 {%0,%1},%2;" : "=f"(lo), "=f"(hi) : "l"(v));
}
__device__ __forceinline__ float frcp(float a) {
    float r; asm("rcp.approx.f32 %0,%1;" : "=f"(r) : "f"(a)); return r;
}

// ---------------- P0: fused prep — nodes + weights + group coefficients --------------
// grid 128 x block 256. Block b owns nodes 8b..8b+7 and groups 2b, 2b+1.
// (a) every block recomputes all 1024 Chebyshev nodes into smem (no global dep)
// (b) warp w computes the f32 log-sum weight of node 8b+w (reference math; the
//     max-normalization in the reference is a COMMON factor across nodes and
//     cancels in num/den, so a fixed LOGC shift replaces the global reduction)
// (c) threads 0..1 build the fp64 group-rational coefficients and pack f32x2.
//     Group g: nodes 4g..4g+3, local var t = x - c:
//       Q(t)  = prod (t - d_i)                     (monic quartic)
//       Pv(t) = sum v_i*w_i * prod_{j!=i}(t - d_j) (cubic)
//       Pw(t) = sum     w_i * prod_{j!=i}(t - d_j) (cubic)
__global__ __launch_bounds__(256) void k_prep(const float* __restrict__ vals,
                                              const float* __restrict__ pr,
                                              const float* __restrict__ pim) {
    __shared__ float snodes[NN];
    __shared__ float sw[8];
    int tid = threadIdx.x;

    // (a) nodes: double cos -> f32 (node precision is load-bearing near clusters)
    #pragma unroll
    for (int i = tid; i < NN; i += 256) {
        double t = (double)i / 1023.0;
        snodes[i] = (float)cos(PI_D * t);
    }
    __syncthreads();

    // (b) weights: one warp per node
    int w  = tid >> 5;
    int ln = tid & 31;
    int j  = blockIdx.x * 8 + w;
    float nj = snodes[j];
    float s = 0.f;
    #pragma unroll 8
    for (int i = ln; i < NN; i += 32)
        if (i != j) s += logf(fabsf(nj - snodes[i]));
    #pragma unroll
    for (int off = 16; off; off >>= 1) s += __shfl_xor_sync(0xffffffffu, s, off);
    if (ln == 0) {
        float ps = 0.f;
        #pragma unroll
        for (int p = 0; p < NPOLES; p++) {
            float dr = nj - pr[p];
            ps += logf(dr * dr + pim[p] * pim[p]);
        }
        float wv = expf(ps - s - LOGC);
        sw[w] = (j & 1) ? -wv : wv;     // sign = (-1)^j (nodes strictly descending)
    }
    __syncthreads();

    // (c) coefficients: 2 groups per block
    if (tid < 2) {
        int g = blockIdx.x * 2 + tid;
        double n[4], d[4], u[4], uv[4];
        #pragma unroll
        for (int i = 0; i < 4; i++) n[i] = (double)snodes[4 * g + i];
        float cf = (float)(0.25 * (n[0] + n[1] + n[2] + n[3]));
        #pragma unroll
        for (int i = 0; i < 4; i++) {
            d[i]  = n[i] - (double)cf;
            u[i]  = (double)sw[4 * tid + i];
            uv[i] = u[i] * (double)vals[4 * g + i];
        }
        double e1 = d[0] + d[1] + d[2] + d[3];
        double e2 = d[0]*d[1] + d[0]*d[2] + d[0]*d[3] + d[1]*d[2] + d[1]*d[3] + d[2]*d[3];
        double e3 = d[0]*d[1]*d[2] + d[0]*d[1]*d[3] + d[0]*d[2]*d[3] + d[1]*d[2]*d[3];
        double e4 = d[0]*d[1]*d[2]*d[3];
        double pv3 = 0, pv2 = 0, pv1 = 0, pv0 = 0;
        double pw3 = 0, pw2 = 0, pw1 = 0, pw0 = 0;
        #pragma unroll
        for (int i = 0; i < 4; i++) {
            double s1 = e1 - d[i];          // elementary syms of the 3 other roots
            double s2 = e2 - d[i] * s1;
            double s3 = e3 - d[i] * s2;
            pv3 += uv[i];  pv2 -= uv[i] * s1;  pv1 += uv[i] * s2;  pv0 -= uv[i] * s3;
            pw3 += u[i];   pw2 -= u[i]  * s1;  pw1 += u[i]  * s2;  pw0 -= u[i]  * s3;
        }
        ull* cc = (ull*)g_coef + (size_t)g * 14;
        float f;
        f = -cf;          cc[0]  = pk2(f, f);
        f = (float)(-e1); cc[1]  = pk2(f, f);   // q3
        f = (float)( e2); cc[2]  = pk2(f, f);   // q2
        f = (float)(-e3); cc[3]  = pk2(f, f);   // q1
        f = (float)( e4); cc[4]  = pk2(f, f);   // q0
        f = (float)pv3;   cc[5]  = pk2(f, f);
        f = (float)pv2;   cc[6]  = pk2(f, f);
        f = (float)pv1;   cc[7]  = pk2(f, f);
        f = (float)pv0;   cc[8]  = pk2(f, f);
        f = (float)pw3;   cc[9]  = pk2(f, f);
        f = (float)pw2;   cc[10] = pk2(f, f);
        f = (float)pw1;   cc[11] = pk2(f, f);
        f = (float)pw0;   cc[12] = pk2(f, f);
        cc[13] = 0ull;                          // pad to 7 x 16B
    }
}

// ---------------- main eval: 4 points (2 packed f32x2 pairs) per thread --------------
// grid 128 x block 256 -> uniform 8 warps (2/SMSP) on 128 SMs. Coefficients are
// double-buffered in registers: group g+1's 7 LDS.128 issue before group g's
// math, hiding the 29-cyc shared latency behind the fma stream.
__global__ __launch_bounds__(256) void k_eval(const float* __restrict__ x,
                                              float* __restrict__ out) {
    __shared__ ulonglong2 sc[(NGROUPS + 1) * 7];   // +1 group pad for prefetch over-read
    {
        const uint4* src = (const uint4*)g_coef;
        uint4* dst = (uint4*)sc;
        #pragma unroll
        for (int i = threadIdx.x; i < NGROUPS * 7; i += 256) dst[i] = src[i];
    }
    __syncthreads();

    int idx = blockIdx.x * 256 + threadIdx.x;       // quad index, 4 consecutive points
    float4 xv = ((const float4*)x)[idx];
    ull xa = pk2(xv.x, xv.y);
    ull xb = pk2(xv.z, xv.w);
    ull numa = 0ull, dena = 0ull, numb = 0ull, denb = 0ull;

    const ulonglong2* cp = sc;
    ulonglong2 c0 = cp[0], c1 = cp[1], c2 = cp[2], c3 = cp[3],
               c4 = cp[4], c5 = cp[5], c6 = cp[6];

    #pragma unroll 4
    for (int g = 0; g < NGROUPS; g++) {
        // prefetch next group's coefficients (pad group makes last iter safe)
        ulonglong2 n0 = cp[7],  n1 = cp[8],  n2 = cp[9],  n3 = cp[10],
                   n4 = cp[11], n5 = cp[12], n6 = cp[13];
        cp += 7;

        ull ta = f2add(xa, c0.x);                   // t = x - c (exact near group)
        ull tb = f2add(xb, c0.x);
        ull qa = f2add(ta, c0.y);                   // monic quartic Horner
        ull qb = f2add(tb, c0.y);
        qa = f2fma(qa, ta, c1.x);   qb = f2fma(qb, tb, c1.x);
        qa = f2fma(qa, ta, c1.y);   qb = f2fma(qb, tb, c1.y);
        qa = f2fma(qa, ta, c2.x);   qb = f2fma(qb, tb, c2.x);
        ull pva = f2fma(c2.y, ta, c3.x);            // cubic Horner (num)
        ull pvb = f2fma(c2.y, tb, c3.x);
        pva = f2fma(pva, ta, c3.y); pvb = f2fma(pvb, tb, c3.y);
        pva = f2fma(pva, ta, c4.x); pvb = f2fma(pvb, tb, c4.x);
        ull pwa = f2fma(c4.y, ta, c5.x);            // cubic Horner (den)
        ull pwb = f2fma(c4.y, tb, c5.x);
        pwa = f2fma(pwa, ta, c5.y); pwb = f2fma(pwb, tb, c5.y);
        pwa = f2fma(pwa, ta, c6.x); pwb = f2fma(pwb, tb, c6.x);
        float qal, qah, qbl, qbh;
        upk2(qa, qal, qah);
        upk2(qb, qbl, qbh);
        ull ra = pk2(frcp(qal), frcp(qah));         // 1 MUFU per 4 nodes per point
        ull rb = pk2(frcp(qbl), frcp(qbh));
        numa = f2fma(pva, ra, numa);
        dena = f2fma(pwa, ra, dena);
        numb = f2fma(pvb, rb, numb);
        denb = f2fma(pwb, rb, denb);

        c0 = n0; c1 = n1; c2 = n2; c3 = n3; c4 = n4; c5 = n5; c6 = n6;
    }

    float n0f, n1f, d0f, d1f;
    float4 o;
    upk2(numa, n0f, n1f); upk2(dena, d0f, d1f);
    o.x = n0f * frcp(d0f);
    o.y = n1f * frcp(d1f);
    upk2(numb, n0f, n1f); upk2(denb, d0f, d1f);
    o.z = n0f * frcp(d0f);
    o.w = n1f * frcp(d1f);
    ((float4*)out)[idx] = o;
}

// ---------------- launch ----------------
extern "C" void kernel_launch(void* const* d_in, const int* in_sizes, int n_in,
                              void* d_out, int out_size) {
    const float* x    = (const float*)d_in[0];
    const float* vals = (const float*)d_in[1];
    const float* pr   = (const float*)d_in[2];
    const float* pim  = (const float*)d_in[3];
    float* out = (float*)d_out;

    k_prep<<<128, 256>>>(vals, pr, pim);
    k_eval<<<128, 256>>>(x, out);
}

// round 5
// speedup vs baseline: 1.2305x; 1.0450x over previous
#include <cuda_runtime.h>
#include <math.h>

#define NN       1024
#define NEVALC   131072
#define NPOLES   8
#define NGROUPS  256          // 4 nodes per group
#define LOGC     700.0f       // fixed log-shift (cancels in num/den); keeps expf in range

typedef unsigned long long ull;

// ---------------- scratch (no allocations allowed) ----------------
__device__ ulonglong2 g_coef[NGROUPS * 7];   // 14 packed-duplicated f32x2 coeffs per group

// ---------------- packed f32x2 helpers (sm_103a) ----------------
__device__ __forceinline__ ull f2fma(ull a, ull b, ull c) {
    ull d; asm("fma.rn.f32x2 %0,%1,%2,%3;" : "=l"(d) : "l"(a), "l"(b), "l"(c)); return d;
}
__device__ __forceinline__ ull f2add(ull a, ull b) {
    ull d; asm("add.rn.f32x2 %0,%1,%2;" : "=l"(d) : "l"(a), "l"(b)); return d;
}
__device__ __forceinline__ ull pk2(float lo, float hi) {
    ull r; asm("mov.b64 %0,{%1,%2};" : "=l"(r) : "f"(lo), "f"(hi)); return r;
}
__device__ __forceinline__ void upk2(ull v, float& lo, float& hi) {
    asm("mov.b64 {%0,%1},%2;" : "=f"(lo), "=f"(hi) : "l"(v));
}
__device__ __forceinline__ float frcp(float a) {
    float r; asm("rcp.approx.f32 %0,%1;" : "=f"(r) : "f"(a)); return r;
}

// ---------------- P0: fused prep — nodes + weights + group coefficients --------------
// grid 128 x block 256. Block b owns nodes 8b..8b+7 and groups 2b, 2b+1.
__global__ __launch_bounds__(256) void k_prep(const float* __restrict__ vals,
                                              const float* __restrict__ pr,
                                              const float* __restrict__ pim) {
    __shared__ float snodes[NN];
    __shared__ float sw[8];
    int tid = threadIdx.x;

    // (a) nodes: fp64 cospi -> f32 (node precision is load-bearing near clusters)
    #pragma unroll
    for (int i = tid; i < NN; i += 256)
        snodes[i] = (float)cospi((double)i / 1023.0);
    __syncthreads();

    // (b) weights: one warp per node; f32 log-sum (reference math). The max-
    // normalization is a COMMON factor and cancels in num/den -> fixed LOGC.
    int w  = tid >> 5;
    int ln = tid & 31;
    int j  = blockIdx.x * 8 + w;
    float nj = snodes[j];
    float s = 0.f;
    #pragma unroll 8
    for (int i = ln; i < NN; i += 32)
        if (i != j) s += logf(fabsf(nj - snodes[i]));
    #pragma unroll
    for (int off = 16; off; off >>= 1) s += __shfl_xor_sync(0xffffffffu, s, off);
    if (ln == 0) {
        float ps = 0.f;
        #pragma unroll
        for (int p = 0; p < NPOLES; p++) {
            float dr = nj - pr[p];
            ps += logf(dr * dr + pim[p] * pim[p]);
        }
        float wv = expf(ps - s - LOGC);
        sw[w] = (j & 1) ? -wv : wv;     // sign = (-1)^j (nodes strictly descending)
    }
    __syncthreads();

    // (c) group-rational coefficients (fp64 build -> f32 packed), 2 groups/block.
    //   Q(t)  = prod (t - d_i)                     (monic quartic)
    //   Pv(t) = sum v_i*w_i * prod_{j!=i}(t - d_j) (cubic)
    //   Pw(t) = sum     w_i * prod_{j!=i}(t - d_j) (cubic)
    if (tid < 2) {
        int g = blockIdx.x * 2 + tid;
        double n[4], d[4], u[4], uv[4];
        #pragma unroll
        for (int i = 0; i < 4; i++) n[i] = (double)snodes[4 * g + i];
        float cf = (float)(0.25 * (n[0] + n[1] + n[2] + n[3]));
        #pragma unroll
        for (int i = 0; i < 4; i++) {
            d[i]  = n[i] - (double)cf;
            u[i]  = (double)sw[4 * tid + i];
            uv[i] = u[i] * (double)vals[4 * g + i];
        }
        double e1 = d[0] + d[1] + d[2] + d[3];
        double e2 = d[0]*d[1] + d[0]*d[2] + d[0]*d[3] + d[1]*d[2] + d[1]*d[3] + d[2]*d[3];
        double e3 = d[0]*d[1]*d[2] + d[0]*d[1]*d[3] + d[0]*d[2]*d[3] + d[1]*d[2]*d[3];
        double e4 = d[0]*d[1]*d[2]*d[3];
        double pv3 = 0, pv2 = 0, pv1 = 0, pv0 = 0;
        double pw3 = 0, pw2 = 0, pw1 = 0, pw0 = 0;
        #pragma unroll
        for (int i = 0; i < 4; i++) {
            double s1 = e1 - d[i];          // elementary syms of the 3 other roots
            double s2 = e2 - d[i] * s1;
            double s3 = e3 - d[i] * s2;
            pv3 += uv[i];  pv2 -= uv[i] * s1;  pv1 += uv[i] * s2;  pv0 -= uv[i] * s3;
            pw3 += u[i];   pw2 -= u[i]  * s1;  pw1 += u[i]  * s2;  pw0 -= u[i]  * s3;
        }
        ull* cc = (ull*)g_coef + (size_t)g * 14;
        float f;
        f = -cf;          cc[0]  = pk2(f, f);
        f = (float)(-e1); cc[1]  = pk2(f, f);   // q3
        f = (float)( e2); cc[2]  = pk2(f, f);   // q2
        f = (float)(-e3); cc[3]  = pk2(f, f);   // q1
        f = (float)( e4); cc[4]  = pk2(f, f);   // q0
        f = (float)pv3;   cc[5]  = pk2(f, f);
        f = (float)pv2;   cc[6]  = pk2(f, f);
        f = (float)pv1;   cc[7]  = pk2(f, f);
        f = (float)pv0;   cc[8]  = pk2(f, f);
        f = (float)pw3;   cc[9]  = pk2(f, f);
        f = (float)pw2;   cc[10] = pk2(f, f);
        f = (float)pw1;   cc[11] = pk2(f, f);
        f = (float)pw0;   cc[12] = pk2(f, f);
        cc[13] = 0ull;                          // pad to 7 x 16B
    }
}

// ---------------- main eval: split-2 over groups, 4 pts per thread-pair --------------
// block 512 = 16 warps (4/SMSP), grid 128 (1 CTA/SM). Threads t and t+256 handle
// the SAME 4 eval points; warps 0-7 accumulate groups 0..127, warps 8-15 groups
// 128..255 (num/den are linear in groups). Upper half deposits partials in smem;
// lower half combines, divides, writes. LDS stays warp-uniform (broadcast).
__global__ __launch_bounds__(512) void k_eval(const float* __restrict__ x,
                                              float* __restrict__ out) {
    __shared__ ulonglong2 sc[(NGROUPS + 1) * 7];   // +1 group pad for prefetch over-read
    __shared__ ull sred[256][4];
    {
        const uint4* src = (const uint4*)g_coef;
        uint4* dst = (uint4*)sc;
        #pragma unroll
        for (int i = threadIdx.x; i < NGROUPS * 7; i += 512) dst[i] = src[i];
    }
    __syncthreads();

    int t    = threadIdx.x;
    int half = t >> 8;                      // 0: groups 0..127, 1: groups 128..255
    int ql   = t & 255;
    int quad = blockIdx.x * 256 + ql;       // 4 consecutive points
    float4 xv = ((const float4*)x)[quad];
    ull xa = pk2(xv.x, xv.y);
    ull xb = pk2(xv.z, xv.w);
    ull numa = 0ull, dena = 0ull, numb = 0ull, denb = 0ull;

    const ulonglong2* cp = sc + half * 128 * 7;
    ulonglong2 c0 = cp[0], c1 = cp[1], c2 = cp[2], c3 = cp[3],
               c4 = cp[4], c5 = cp[5], c6 = cp[6];

    #pragma unroll 4
    for (int g = 0; g < 128; g++) {
        // prefetch next group's coefficients (pad group makes last iter safe)
        ulonglong2 n0 = cp[7],  n1 = cp[8],  n2 = cp[9],  n3 = cp[10],
                   n4 = cp[11], n5 = cp[12], n6 = cp[13];
        cp += 7;

        ull ta = f2add(xa, c0.x);                   // t = x - c (exact near group)
        ull tb = f2add(xb, c0.x);
        ull qa = f2add(ta, c0.y);                   // monic quartic Horner
        ull qb = f2add(tb, c0.y);
        qa = f2fma(qa, ta, c1.x);   qb = f2fma(qb, tb, c1.x);
        qa = f2fma(qa, ta, c1.y);   qb = f2fma(qb, tb, c1.y);
        qa = f2fma(qa, ta, c2.x);   qb = f2fma(qb, tb, c2.x);
        ull pva = f2fma(c2.y, ta, c3.x);            // cubic Horner (num)
        ull pvb = f2fma(c2.y, tb, c3.x);
        pva = f2fma(pva, ta, c3.y); pvb = f2fma(pvb, tb, c3.y);
        pva = f2fma(pva, ta, c4.x); pvb = f2fma(pvb, tb, c4.x);
        ull pwa = f2fma(c4.y, ta, c5.x);            // cubic Horner (den)
        ull pwb = f2fma(c4.y, tb, c5.x);
        pwa = f2fma(pwa, ta, c5.y); pwb = f2fma(pwb, tb, c5.y);
        pwa = f2fma(pwa, ta, c6.x); pwb = f2fma(pwb, tb, c6.x);
        float qal, qah, qbl, qbh;
        upk2(qa, qal, qah);
        upk2(qb, qbl, qbh);
        ull ra = pk2(frcp(qal), frcp(qah));         // 1 MUFU per 4 nodes per point
        ull rb = pk2(frcp(qbl), frcp(qbh));
        numa = f2fma(pva, ra, numa);
        dena = f2fma(pwa, ra, dena);
        numb = f2fma(pvb, rb, numb);
        denb = f2fma(pwb, rb, denb);

        c0 = n0; c1 = n1; c2 = n2; c3 = n3; c4 = n4; c5 = n5; c6 = n6;
    }

    if (half) {
        sred[ql][0] = numa; sred[ql][1] = dena;
        sred[ql][2] = numb; sred[ql][3] = denb;
    }
    __syncthreads();
    if (!half) {
        numa = f2add(numa, sred[ql][0]);
        dena = f2add(dena, sred[ql][1]);
        numb = f2add(numb, sred[ql][2]);
        denb = f2add(denb, sred[ql][3]);
        float n0f, n1f, d0f, d1f;
        float4 o;
        upk2(numa, n0f, n1f); upk2(dena, d0f, d1f);
        o.x = n0f * frcp(d0f);
        o.y = n1f * frcp(d1f);
        upk2(numb, n0f, n1f); upk2(denb, d0f, d1f);
        o.z = n0f * frcp(d0f);
        o.w = n1f * frcp(d1f);
        ((float4*)out)[quad] = o;
    }
}

// ---------------- launch ----------------
extern "C" void kernel_launch(void* const* d_in, const int* in_sizes, int n_in,
                              void* d_out, int out_size) {
    const float* x    = (const float*)d_in[0];
    const float* vals = (const float*)d_in[1];
    const float* pr   = (const float*)d_in[2];
    const float* pim  = (const float*)d_in[3];
    float* out = (float*)d_out;

    k_prep<<<128, 256>>>(vals, pr, pim);
    k_eval<<<128, 512>>>(x, out);
}

// round 6
// speedup vs baseline: 1.2366x; 1.0049x over previous
#include <cuda_runtime.h>
#include <math.h>

#define NN       1024
#define NEVALC   131072
#define NPOLES   8
#define NGROUPS  256          // 4 nodes per group
#define LOGC     700.0f       // fixed log-shift (cancels in num/den); keeps expf in range

typedef unsigned long long ull;

// ---------------- scratch (no allocations allowed) ----------------
__device__ float      g_nodes[NN];
__device__ ulonglong2 g_coef[NGROUPS * 7];   // 14 packed-duplicated f32x2 coeffs per group

// ---------------- packed f32x2 helpers (sm_103a) ----------------
__device__ __forceinline__ ull f2fma(ull a, ull b, ull c) {
    ull d; asm("fma.rn.f32x2 %0,%1,%2,%3;" : "=l"(d) : "l"(a), "l"(b), "l"(c)); return d;
}
__device__ __forceinline__ ull f2add(ull a, ull b) {
    ull d; asm("add.rn.f32x2 %0,%1,%2;" : "=l"(d) : "l"(a), "l"(b)); return d;
}
__device__ __forceinline__ ull pk2(float lo, float hi) {
    ull r; asm("mov.b64 %0,{%1,%2};" : "=l"(r) : "f"(lo), "f"(hi)); return r;
}
__device__ __forceinline__ void upk2(ull v, float& lo, float& hi) {
    asm("mov.b64 {%0,%1},%2;" : "=f"(lo), "=f"(hi) : "l"(v));
}
__device__ __forceinline__ float frcp(float a) {
    float r; asm("rcp.approx.f32 %0,%1;" : "=f"(r) : "f"(a)); return r;
}

// ---------------- P0: Chebyshev nodes, computed ONCE (fp64 cospi -> f32) ------------
// Node bit patterns must match the reference's f32 cos values; fp64-rounded has
// matched at rel_err 6.65e-5 across all passing rounds — do not change the math.
__global__ void k_nodes() {
    int i = blockIdx.x * blockDim.x + threadIdx.x;
    if (i < NN) g_nodes[i] = (float)cospi((double)i / 1023.0);
}

// ---------------- P1: weights + group coefficients (no fp64 cospi here) -------------
// grid 128 x block 256. Block b owns nodes 8b..8b+7 and groups 2b, 2b+1.
__global__ __launch_bounds__(256) void k_prep(const float* __restrict__ vals,
                                              const float* __restrict__ pr,
                                              const float* __restrict__ pim) {
    __shared__ float snodes[NN];
    __shared__ float sw[8];
    int tid = threadIdx.x;

    // load the shared node table (float4, one pass)
    {
        const float4* src = (const float4*)g_nodes;
        float4* dst = (float4*)snodes;
        dst[tid] = src[tid];                 // 256 threads x 4 floats = 1024
    }
    __syncthreads();

    // weights: one warp per node; f32 log-sum (reference math). The max-
    // normalization is a COMMON factor and cancels in num/den -> fixed LOGC.
    int w  = tid >> 5;
    int ln = tid & 31;
    int j  = blockIdx.x * 8 + w;
    float nj = snodes[j];
    float s = 0.f;
    #pragma unroll 8
    for (int i = ln; i < NN; i += 32)
        if (i != j) s += logf(fabsf(nj - snodes[i]));
    #pragma unroll
    for (int off = 16; off; off >>= 1) s += __shfl_xor_sync(0xffffffffu, s, off);
    if (ln == 0) {
        float ps = 0.f;
        #pragma unroll
        for (int p = 0; p < NPOLES; p++) {
            float dr = nj - pr[p];
            ps += logf(dr * dr + pim[p] * pim[p]);
        }
        float wv = expf(ps - s - LOGC);
        sw[w] = (j & 1) ? -wv : wv;     // sign = (-1)^j (nodes strictly descending)
    }
    __syncthreads();

    // group-rational coefficients (fp64 build -> f32 packed), 2 groups/block.
    //   Q(t)  = prod (t - d_i)                     (monic quartic)
    //   Pv(t) = sum v_i*w_i * prod_{j!=i}(t - d_j) (cubic)
    //   Pw(t) = sum     w_i * prod_{j!=i}(t - d_j) (cubic)
    if (tid < 2) {
        int g = blockIdx.x * 2 + tid;
        double n[4], d[4], u[4], uv[4];
        #pragma unroll
        for (int i = 0; i < 4; i++) n[i] = (double)snodes[4 * g + i];
        float cf = (float)(0.25 * (n[0] + n[1] + n[2] + n[3]));
        #pragma unroll
        for (int i = 0; i < 4; i++) {
            d[i]  = n[i] - (double)cf;
            u[i]  = (double)sw[4 * tid + i];
            uv[i] = u[i] * (double)vals[4 * g + i];
        }
        double e1 = d[0] + d[1] + d[2] + d[3];
        double e2 = d[0]*d[1] + d[0]*d[2] + d[0]*d[3] + d[1]*d[2] + d[1]*d[3] + d[2]*d[3];
        double e3 = d[0]*d[1]*d[2] + d[0]*d[1]*d[3] + d[0]*d[2]*d[3] + d[1]*d[2]*d[3];
        double e4 = d[0]*d[1]*d[2]*d[3];
        double pv3 = 0, pv2 = 0, pv1 = 0, pv0 = 0;
        double pw3 = 0, pw2 = 0, pw1 = 0, pw0 = 0;
        #pragma unroll
        for (int i = 0; i < 4; i++) {
            double s1 = e1 - d[i];          // elementary syms of the 3 other roots
            double s2 = e2 - d[i] * s1;
            double s3 = e3 - d[i] * s2;
            pv3 += uv[i];  pv2 -= uv[i] * s1;  pv1 += uv[i] * s2;  pv0 -= uv[i] * s3;
            pw3 += u[i];   pw2 -= u[i]  * s1;  pw1 += u[i]  * s2;  pw0 -= u[i]  * s3;
        }
        ull* cc = (ull*)g_coef + (size_t)g * 14;
        float f;
        f = -cf;          cc[0]  = pk2(f, f);
        f = (float)(-e1); cc[1]  = pk2(f, f);   // q3
        f = (float)( e2); cc[2]  = pk2(f, f);   // q2
        f = (float)(-e3); cc[3]  = pk2(f, f);   // q1
        f = (float)( e4); cc[4]  = pk2(f, f);   // q0
        f = (float)pv3;   cc[5]  = pk2(f, f);
        f = (float)pv2;   cc[6]  = pk2(f, f);
        f = (float)pv1;   cc[7]  = pk2(f, f);
        f = (float)pv0;   cc[8]  = pk2(f, f);
        f = (float)pw3;   cc[9]  = pk2(f, f);
        f = (float)pw2;   cc[10] = pk2(f, f);
        f = (float)pw1;   cc[11] = pk2(f, f);
        f = (float)pw0;   cc[12] = pk2(f, f);
        cc[13] = 0ull;                          // pad to 7 x 16B
    }
}

// ---------------- main eval: split-4 over groups, 4 pts per thread-quartet ----------
// block 1024 = 32 warps (8/SMSP), grid 128 (1 CTA/SM). Threads t, t+256, t+512,
// t+768 handle the SAME 4 eval points; partition p accumulates groups
// 64p..64p+63 (num/den are linear in groups). Partitions 1-3 deposit partials
// in smem; partition 0 combines, divides, writes. LDS stays warp-uniform.
__global__ __launch_bounds__(1024) void k_eval(const float* __restrict__ x,
                                               float* __restrict__ out) {
    __shared__ ulonglong2 sc[NGROUPS * 7];     // 28 KB coeffs, broadcast reads
    __shared__ ull sred[3][256][4];            // 24 KB partials
    {
        const uint4* src = (const uint4*)g_coef;
        uint4* dst = (uint4*)sc;
        #pragma unroll
        for (int i = threadIdx.x; i < NGROUPS * 7; i += 1024) dst[i] = src[i];
    }
    __syncthreads();

    int t    = threadIdx.x;
    int part = t >> 8;                      // group partition 0..3
    int ql   = t & 255;
    int quad = blockIdx.x * 256 + ql;       // 4 consecutive points
    float4 xv = ((const float4*)x)[quad];
    ull xa = pk2(xv.x, xv.y);
    ull xb = pk2(xv.z, xv.w);
    ull numa = 0ull, dena = 0ull, numb = 0ull, denb = 0ull;

    const ulonglong2* cp = sc + part * 64 * 7;

    #pragma unroll 8
    for (int g = 0; g < 64; g++) {
        ulonglong2 c0 = cp[0], c1 = cp[1], c2 = cp[2], c3 = cp[3],
                   c4 = cp[4], c5 = cp[5], c6 = cp[6];
        cp += 7;

        ull ta = f2add(xa, c0.x);                   // t = x - c (exact near group)
        ull tb = f2add(xb, c0.x);
        ull qa = f2add(ta, c0.y);                   // monic quartic Horner
        ull qb = f2add(tb, c0.y);
        qa = f2fma(qa, ta, c1.x);   qb = f2fma(qb, tb, c1.x);
        qa = f2fma(qa, ta, c1.y);   qb = f2fma(qb, tb, c1.y);
        qa = f2fma(qa, ta, c2.x);   qb = f2fma(qb, tb, c2.x);
        ull pva = f2fma(c2.y, ta, c3.x);            // cubic Horner (num)
        ull pvb = f2fma(c2.y, tb, c3.x);
        pva = f2fma(pva, ta, c3.y); pvb = f2fma(pvb, tb, c3.y);
        pva = f2fma(pva, ta, c4.x); pvb = f2fma(pvb, tb, c4.x);
        ull pwa = f2fma(c4.y, ta, c5.x);            // cubic Horner (den)
        ull pwb = f2fma(c4.y, tb, c5.x);
        pwa = f2fma(pwa, ta, c5.y); pwb = f2fma(pwb, tb, c5.y);
        pwa = f2fma(pwa, ta, c6.x); pwb = f2fma(pwb, tb, c6.x);
        float qal, qah, qbl, qbh;
        upk2(qa, qal, qah);
        upk2(qb, qbl, qbh);
        ull ra = pk2(frcp(qal), frcp(qah));         // 1 MUFU per 4 nodes per point
        ull rb = pk2(frcp(qbl), frcp(qbh));
        numa = f2fma(pva, ra, numa);
        dena = f2fma(pwa, ra, dena);
        numb = f2fma(pvb, rb, numb);
        denb = f2fma(pwb, rb, denb);
    }

    if (part) {
        sred[part - 1][ql][0] = numa; sred[part - 1][ql][1] = dena;
        sred[part - 1][ql][2] = numb; sred[part - 1][ql][3] = denb;
    }
    __syncthreads();
    if (part == 0) {
        #pragma unroll
        for (int p = 0; p < 3; p++) {
            numa = f2add(numa, sred[p][ql][0]);
            dena = f2add(dena, sred[p][ql][1]);
            numb = f2add(numb, sred[p][ql][2]);
            denb = f2add(denb, sred[p][ql][3]);
        }
        float n0f, n1f, d0f, d1f;
        float4 o;
        upk2(numa, n0f, n1f); upk2(dena, d0f, d1f);
        o.x = n0f * frcp(d0f);
        o.y = n1f * frcp(d1f);
        upk2(numb, n0f, n1f); upk2(denb, d0f, d1f);
        o.z = n0f * frcp(d0f);
        o.w = n1f * frcp(d1f);
        ((float4*)out)[quad] = o;
    }
}

// ---------------- launch ----------------
extern "C" void kernel_launch(void* const* d_in, const int* in_sizes, int n_in,
                              void* d_out, int out_size) {
    const float* x    = (const float*)d_in[0];
    const float* vals = (const float*)d_in[1];
    const float* pr   = (const float*)d_in[2];
    const float* pim  = (const float*)d_in[3];
    float* out = (float*)d_out;

    k_nodes<<<8, 128>>>();
    k_prep <<<128, 256>>>(vals, pr, pim);
    k_eval <<<128, 1024>>>(x, out);
}

// round 7
// speedup vs baseline: 1.4213x; 1.1494x over previous
#include <cuda_runtime.h>
#include <math.h>

#define NN       1024
#define NEVALC   131072
#define NPOLES   8
#define NGROUPS  256          // 4 nodes per group
#define LOGC     700.0f      // fixed log-shift (cancels in num/den); keeps expf in range

typedef unsigned long long ull;

// ---------------- compile-time Chebyshev nodes --------------------------------------
// Nodes are input-independent. constexpr cospi (Taylor, |err| ~1e-17) reproduces the
// fp64-cos -> f32 node bits used by every passing round. No runtime kernel needed.
constexpr double CPI = 3.141592653589793238462643383279502884;
constexpr double ccos_t(double z) {            // |z| <= pi/4
    double t = 1.0, s = 1.0, z2 = z * z;
    for (int k = 1; k <= 12; k++) { t *= -z2 / ((2.0 * k - 1.0) * (2.0 * k)); s += t; }
    return s;
}
constexpr double csin_t(double z) {            // |z| <= pi/4
    double t = z, s = z, z2 = z * z;
    for (int k = 1; k <= 12; k++) { t *= -z2 / ((2.0 * k) * (2.0 * k + 1.0)); s += t; }
    return s;
}
constexpr double cospi_c(double x) {           // x in [0,1]
    double r = x; bool neg = false;
    if (r > 0.5) { r = 1.0 - r; neg = true; }
    double v = (r <= 0.25) ? ccos_t(CPI * r) : csin_t(CPI * (0.5 - r));
    return neg ? -v : v;
}
struct alignas(16) NodeTab { float v[NN]; };
constexpr NodeTab mk_nodes() {
    NodeTab n{};
    for (int i = 0; i < NN; i++) n.v[i] = (float)cospi_c((double)i / 1023.0);
    return n;
}
__device__ constexpr NodeTab c_nodes = mk_nodes();

// ---------------- scratch (no allocations allowed) ----------------
__device__ ulonglong2 g_coef[NGROUPS * 7];   // 14 packed-duplicated f32x2 coeffs per group

// ---------------- packed f32x2 helpers (sm_103a) ----------------
__device__ __forceinline__ ull f2fma(ull a, ull b, ull c) {
    ull d; asm("fma.rn.f32x2 %0,%1,%2,%3;" : "=l"(d) : "l"(a), "l"(b), "l"(c)); return d;
}
__device__ __forceinline__ ull f2add(ull a, ull b) {
    ull d; asm("add.rn.f32x2 %0,%1,%2;" : "=l"(d) : "l"(a), "l"(b)); return d;
}
__device__ __forceinline__ ull pk2(float lo, float hi) {
    ull r; asm("mov.b64 %0,{%1,%2};" : "=l"(r) : "f"(lo), "f"(hi)); return r;
}
__device__ __forceinline__ void upk2(ull v, float& lo, float& hi) {
    asm("mov.b64 {%0,%1},%2;" : "=f"(lo), "=f"(hi) : "l"(v));
}
// packed reciprocal: both rcps + repack inside one asm block
__device__ __forceinline__ ull f2rcp(ull q) {
    ull r;
    asm("{.reg .f32 lo, hi;\n\t"
        "mov.b64 {lo, hi}, %1;\n\t"
        "rcp.approx.f32 lo, lo;\n\t"
        "rcp.approx.f32 hi, hi;\n\t"
        "mov.b64 %0, {lo, hi};}"
        : "=l"(r) : "l"(q));
    return r;
}
__device__ __forceinline__ float frcp(float a) {
    float r; asm("rcp.approx.f32 %0,%1;" : "=f"(r) : "f"(a)); return r;
}

// ---------------- P0: weights + group coefficients ----------------------------------
// grid 128 x block 256. Block b owns nodes 8b..8b+7 and groups 2b, 2b+1.
__global__ __launch_bounds__(256) void k_prep(const float* __restrict__ vals,
                                              const float* __restrict__ pr,
                                              const float* __restrict__ pim) {
    __shared__ float snodes[NN];
    __shared__ float sw[8];
    int tid = threadIdx.x;

    // node table from the compile-time constant (L1/const cached)
    {
        const float4* src = (const float4*)c_nodes.v;
        float4* dst = (float4*)snodes;
        dst[tid] = src[tid];                 // 256 threads x 4 floats = 1024
    }
    __syncthreads();

    // weights: one warp per node; f32 log-sum (reference math). The max-
    // normalization is a COMMON factor and cancels in num/den -> fixed LOGC.
    int w  = tid >> 5;
    int ln = tid & 31;
    int j  = blockIdx.x * 8 + w;
    float nj = snodes[j];
    float s = 0.f;
    #pragma unroll 8
    for (int i = ln; i < NN; i += 32)
        if (i != j) s += logf(fabsf(nj - snodes[i]));
    #pragma unroll
    for (int off = 16; off; off >>= 1) s += __shfl_xor_sync(0xffffffffu, s, off);
    if (ln == 0) {
        float ps = 0.f;
        #pragma unroll
        for (int p = 0; p < NPOLES; p++) {
            float dr = nj - pr[p];
            ps += logf(dr * dr + pim[p] * pim[p]);
        }
        float wv = expf(ps - s - LOGC);
        sw[w] = (j & 1) ? -wv : wv;     // sign = (-1)^j (nodes strictly descending)
    }
    __syncthreads();

    // group-rational coefficients (fp64 build -> f32 packed), 2 groups/block.
    //   Q(t)  = prod (t - d_i)                     (monic quartic)
    //   Pv(t) = sum v_i*w_i * prod_{j!=i}(t - d_j) (cubic)
    //   Pw(t) = sum     w_i * prod_{j!=i}(t - d_j) (cubic)
    if (tid < 2) {
        int g = blockIdx.x * 2 + tid;
        double n[4], d[4], u[4], uv[4];
        #pragma unroll
        for (int i = 0; i < 4; i++) n[i] = (double)snodes[4 * g + i];
        float cf = (float)(0.25 * (n[0] + n[1] + n[2] + n[3]));
        #pragma unroll
        for (int i = 0; i < 4; i++) {
            d[i]  = n[i] - (double)cf;
            u[i]  = (double)sw[4 * tid + i];
            uv[i] = u[i] * (double)vals[4 * g + i];
        }
        double e1 = d[0] + d[1] + d[2] + d[3];
        double e2 = d[0]*d[1] + d[0]*d[2] + d[0]*d[3] + d[1]*d[2] + d[1]*d[3] + d[2]*d[3];
        double e3 = d[0]*d[1]*d[2] + d[0]*d[1]*d[3] + d[0]*d[2]*d[3] + d[1]*d[2]*d[3];
        double e4 = d[0]*d[1]*d[2]*d[3];
        double pv3 = 0, pv2 = 0, pv1 = 0, pv0 = 0;
        double pw3 = 0, pw2 = 0, pw1 = 0, pw0 = 0;
        #pragma unroll
        for (int i = 0; i < 4; i++) {
            double s1 = e1 - d[i];          // elementary syms of the 3 other roots
            double s2 = e2 - d[i] * s1;
            double s3 = e3 - d[i] * s2;
            pv3 += uv[i];  pv2 -= uv[i] * s1;  pv1 += uv[i] * s2;  pv0 -= uv[i] * s3;
            pw3 += u[i];   pw2 -= u[i]  * s1;  pw1 += u[i]  * s2;  pw0 -= u[i]  * s3;
        }
        ull* cc = (ull*)g_coef + (size_t)g * 14;
        float f;
        f = -cf;          cc[0]  = pk2(f, f);
        f = (float)(-e1); cc[1]  = pk2(f, f);   // q3
        f = (float)( e2); cc[2]  = pk2(f, f);   // q2
        f = (float)(-e3); cc[3]  = pk2(f, f);   // q1
        f = (float)( e4); cc[4]  = pk2(f, f);   // q0
        f = (float)pv3;   cc[5]  = pk2(f, f);
        f = (float)pv2;   cc[6]  = pk2(f, f);
        f = (float)pv1;   cc[7]  = pk2(f, f);
        f = (float)pv0;   cc[8]  = pk2(f, f);
        f = (float)pw3;   cc[9]  = pk2(f, f);
        f = (float)pw2;   cc[10] = pk2(f, f);
        f = (float)pw1;   cc[11] = pk2(f, f);
        f = (float)pw0;   cc[12] = pk2(f, f);
        cc[13] = 0ull;                          // pad to 7 x 16B
    }
}

// ---------------- main eval: 8 pts/thread (4 pairs), split-4 over groups ------------
// block 512 = 4 partitions x 128 point-lanes, grid 128 (1 CTA/SM, 16 warps).
// Lane l handles quads (bid*256 + l) and (bid*256 + 128 + l); partition p
// accumulates groups 64p..64p+63 (num/den are linear in groups). Partitions 1-3
// deposit partials in smem (reusing the coeff buffer); partition 0 combines.
// 52 f32x2 fma-ops per 7 LDS per iteration -> fma-pipe-bound by design.
__global__ __launch_bounds__(512) void k_eval(const float* __restrict__ x,
                                              float* __restrict__ out) {
    __shared__ ulonglong2 sc[NGROUPS * 7];     // 28 KB coeffs (reused as reduction buf)
    {
        const uint4* src = (const uint4*)g_coef;
        uint4* dst = (uint4*)sc;
        #pragma unroll
        for (int i = threadIdx.x; i < NGROUPS * 7; i += 512) dst[i] = src[i];
    }
    __syncthreads();

    int t    = threadIdx.x;
    int part = t >> 7;                      // group partition 0..3
    int lane = t & 127;                     // point-lane
    int quad0 = blockIdx.x * 256 + lane;    // coalesced float4 accesses
    int quad1 = quad0 + 128;
    float4 a = ((const float4*)x)[quad0];
    float4 b = ((const float4*)x)[quad1];
    ull xp0 = pk2(a.x, a.y), xp1 = pk2(a.z, a.w);
    ull xp2 = pk2(b.x, b.y), xp3 = pk2(b.z, b.w);
    ull nm0 = 0, dn0 = 0, nm1 = 0, dn1 = 0, nm2 = 0, dn2 = 0, nm3 = 0, dn3 = 0;

    const ulonglong2* cp = sc + part * 64 * 7;

    #pragma unroll 4
    for (int g = 0; g < 64; g++) {
        ulonglong2 c0 = cp[0], c1 = cp[1], c2 = cp[2], c3 = cp[3],
                   c4 = cp[4], c5 = cp[5], c6 = cp[6];
        cp += 7;

        #define GRP(XP, NM, DN)                                             \
        {                                                                   \
            ull tt = f2add(XP, c0.x);         /* t = x - c */               \
            ull q  = f2add(tt, c0.y);         /* monic quartic Horner */    \
            q  = f2fma(q,  tt, c1.x);                                       \
            q  = f2fma(q,  tt, c1.y);                                       \
            q  = f2fma(q,  tt, c2.x);                                       \
            ull pv = f2fma(c2.y, tt, c3.x);   /* cubic Horner (num) */      \
            pv = f2fma(pv, tt, c3.y);                                       \
            pv = f2fma(pv, tt, c4.x);                                       \
            ull pw = f2fma(c4.y, tt, c5.x);   /* cubic Horner (den) */      \
            pw = f2fma(pw, tt, c5.y);                                       \
            pw = f2fma(pw, tt, c6.x);                                       \
            ull r = f2rcp(q);                 /* 2 MUFU per 4 nodes/pair */ \
            NM = f2fma(pv, r, NM);                                          \
            DN = f2fma(pw, r, DN);                                          \
        }
        GRP(xp0, nm0, dn0)
        GRP(xp1, nm1, dn1)
        GRP(xp2, nm2, dn2)
        GRP(xp3, nm3, dn3)
        #undef GRP
    }

    // cross-partition reduction: reuse sc as the partial buffer (all coeff
    // reads are complete after this barrier).
    __syncthreads();
    ull (*sred)[128][8] = (ull(*)[128][8])sc;   // 3 x 128 x 8 x 8B = 24 KB <= 28 KB
    if (part) {
        ull* dst = sred[part - 1][lane];
        dst[0] = nm0; dst[1] = dn0; dst[2] = nm1; dst[3] = dn1;
        dst[4] = nm2; dst[5] = dn2; dst[6] = nm3; dst[7] = dn3;
    }
    __syncthreads();
    if (part == 0) {
        #pragma unroll
        for (int p = 0; p < 3; p++) {
            const ull* s = sred[p][lane];
            nm0 = f2add(nm0, s[0]); dn0 = f2add(dn0, s[1]);
            nm1 = f2add(nm1, s[2]); dn1 = f2add(dn1, s[3]);
            nm2 = f2add(nm2, s[4]); dn2 = f2add(dn2, s[5]);
            nm3 = f2add(nm3, s[6]); dn3 = f2add(dn3, s[7]);
        }
        float n0, n1, d0, d1;
        float4 o;
        upk2(nm0, n0, n1); upk2(dn0, d0, d1);
        o.x = n0 * frcp(d0); o.y = n1 * frcp(d1);
        upk2(nm1, n0, n1); upk2(dn1, d0, d1);
        o.z = n0 * frcp(d0); o.w = n1 * frcp(d1);
        ((float4*)out)[quad0] = o;
        upk2(nm2, n0, n1); upk2(dn2, d0, d1);
        o.x = n0 * frcp(d0); o.y = n1 * frcp(d1);
        upk2(nm3, n0, n1); upk2(dn3, d0, d1);
        o.z = n0 * frcp(d0); o.w = n1 * frcp(d1);
        ((float4*)out)[quad1] = o;
    }
}

// ---------------- launch ----------------
extern "C" void kernel_launch(void* const* d_in, const int* in_sizes, int n_in,
                              void* d_out, int out_size) {
    const float* x    = (const float*)d_in[0];
    const float* vals = (const float*)d_in[1];
    const float* pr   = (const float*)d_in[2];
    const float* pim  = (const float*)d_in[3];
    float* out = (float*)d_out;

    k_prep<<<128, 256>>>(vals, pr, pim);
    k_eval<<<128, 512>>>(x, out);
}